// round 3
// baseline (speedup 1.0000x reference)
#include <cuda_runtime.h>
#include <math.h>

#define BB 4
#define NN 4096
#define DD 8
#define KK 64              /* instance ids */
#define CC 32              /* chunks per batch */
#define CHUNK 128          /* elements per chunk == threads */
#define TILE 128
#define TMAX (NN / TILE)   /* 32 */
#define TOTAL_REP_BLOCKS (TMAX * TMAX * BB)

#define LOG2E      1.4426950408889634f
#define TWO_LOG2E  2.8853900817779268f
#define LN2F       0.6931471805599453f

// ---------------- scratch (no allocations allowed) ----------------
__device__ float g_cp_emb[BB][NN][DD];   // compacted CP embeddings
__device__ float g_cp_sq2[BB][NN];       // compacted |e|^2 * log2(e)
__device__ int   g_pos   [BB];           // compaction ticket -> pos (reset by k_rep finalizer)
__device__ int   g_cntc  [BB][CC][KK];   // per-chunk per-segment counts
__device__ int   g_firstc[BB][CC][KK];   // per-chunk per-segment first-CP index
__device__ float g_segc  [BB][CC][KK];   // per-chunk per-segment d2 sums
__device__ float g_bce1c [BB][CC];
__device__ float g_bce0c [BB][CC];
__device__ float g_partial[BB];          // bce + attraction (per batch)
__device__ int   g_validb[BB];
__device__ float g_repsum[BB];
__device__ int   g_arrive[BB];           // phase-A arrival counters
__device__ int   g_bdone [BB];           // phase-B completion counters
__device__ int   g_done;                 // rep-block completion counter

__device__ __forceinline__ float ex2f(float x) {
    float r; asm("ex2.approx.ftz.f32 %0, %1;" : "=f"(r) : "f"(x)); return r;
}
__device__ __forceinline__ float lg2f(float x) {
    float r; asm("lg2.approx.f32 %0, %1;" : "=f"(r) : "f"(x)); return r;
}
__device__ __forceinline__ float softplus_f(float x) {
    // log(1+e^x) = max(x,0) + ln2 * log2(1 + 2^(-|x|*log2e))
    float e = ex2f(-fabsf(x) * LOG2E);
    return fmaxf(x, 0.f) + LN2F * lg2f(1.f + e);
}

// ============ kernel 1 (fused): stats + compaction + attraction + per-batch reduce ============
__global__ void __launch_bounds__(CHUNK) k_fused(const float* __restrict__ beta,
                                                 const float* __restrict__ embed,
                                                 const int*   __restrict__ sid,
                                                 const int*   __restrict__ iscp)
{
    const int c   = blockIdx.x;
    const int b   = blockIdx.y;
    const int tid = threadIdx.x;
    const int i   = c * CHUNK + tid;
    const int g   = b * NN + i;
    const int lane = tid & 31;
    const int wrp  = tid >> 5;          // 0..3

    __shared__ int   s_cnt[KK];
    __shared__ int   s_first[KK];
    __shared__ int   s_gfirst[KK];
    __shared__ float s_cpe[KK][DD];
    __shared__ float s_seg[KK];
    __shared__ float s_red[3][CHUNK / 32];
    __shared__ int   s_flag;

    if (tid < KK) { s_cnt[tid] = 0; s_first[tid] = NN; }
    __syncthreads();

    // ---------------- phase A ----------------
    const int   s  = sid[g];
    const int   cp = iscp[g];
    const float bt = beta[g];

    atomicAdd(&s_cnt[s], 1);
    float l1 = 0.f, l0 = 0.f;
    if (cp == 1) { atomicMin(&s_first[s], i); l1 = softplus_f(-bt); }
    else         { l0 = softplus_f(bt); }

    // warp-aggregated compaction ticket (integer -> exact pos count)
    const unsigned bal = __ballot_sync(0xffffffffu, cp == 1);
    if (bal) {
        const int nw = __popc(bal);
        const int leader = __ffs(bal) - 1;
        int base = 0;
        if (lane == leader) base = atomicAdd(&g_pos[b], nw);
        base = __shfl_sync(0xffffffffu, base, leader);
        if (cp == 1) {
            const int w = base + __popc(bal & ((1u << lane) - 1u));
            const float4* e = (const float4*)&embed[(size_t)g * DD];
            float4 a = e[0], d = e[1];
            float sq = a.x*a.x + a.y*a.y + a.z*a.z + a.w*a.w
                     + d.x*d.x + d.y*d.y + d.z*d.z + d.w*d.w;
            *(float4*)&g_cp_emb[b][w][0] = a;
            *(float4*)&g_cp_emb[b][w][4] = d;
            g_cp_sq2[b][w] = sq * LOG2E;
        }
    }

    // BCE partial reduce (fixed order)
    #pragma unroll
    for (int off = 16; off; off >>= 1) {
        l1 += __shfl_down_sync(0xffffffffu, l1, off);
        l0 += __shfl_down_sync(0xffffffffu, l0, off);
    }
    if (lane == 0) { s_red[0][wrp] = l1; s_red[1][wrp] = l0; }
    __syncthreads();

    if (tid < KK) { g_cntc[b][c][tid] = s_cnt[tid]; g_firstc[b][c][tid] = s_first[tid]; }
    if (tid == 0) {
        float S1 = 0.f, S0 = 0.f;
        #pragma unroll
        for (int w = 0; w < CHUNK / 32; w++) { S1 += s_red[0][w]; S0 += s_red[1][w]; }
        g_bce1c[b][c] = S1;
        g_bce0c[b][c] = S0;
    }

    // ---------------- per-batch barrier ----------------
    __threadfence();                    // release phase-A writes
    if (tid == 0) {
        atomicAdd(&g_arrive[b], 1);
        while (atomicAdd(&g_arrive[b], 0) < CC) { }
        s_flag = 1;
    }
    __syncthreads();
    __threadfence();                    // acquire

    // ---------------- phase B prep: global firsts + anchor embeddings ----------------
    if (tid < KK) {
        int f = NN;
        #pragma unroll
        for (int cc = 0; cc < CC; cc++) f = min(f, g_firstc[b][cc][tid]);
        s_gfirst[tid] = f;
        s_seg[tid]    = 0.f;
        if (f < NN) {
            const float4* e = (const float4*)&embed[((size_t)b * NN + f) * DD];
            *(float4*)&s_cpe[tid][0] = e[0];
            *(float4*)&s_cpe[tid][4] = e[1];
        }
    }
    __syncthreads();

    // ---------------- phase B: attraction d2 segment sums ----------------
    if (s_gfirst[s] < NN) {
        const float4* e = (const float4*)&embed[(size_t)g * DD];
        float4 a = e[0], d = e[1];
        float x0 = a.x - s_cpe[s][0], x1 = a.y - s_cpe[s][1];
        float x2 = a.z - s_cpe[s][2], x3 = a.w - s_cpe[s][3];
        float x4 = d.x - s_cpe[s][4], x5 = d.y - s_cpe[s][5];
        float x6 = d.z - s_cpe[s][6], x7 = d.w - s_cpe[s][7];
        float d2 = x0*x0 + x1*x1 + x2*x2 + x3*x3 + x4*x4 + x5*x5 + x6*x6 + x7*x7;
        atomicAdd(&s_seg[s], d2);
    }
    __syncthreads();
    if (tid < KK) g_segc[b][c][tid] = s_seg[tid];

    // ---------------- per-batch completion: last block reduces ----------------
    __threadfence();
    if (tid == 0) {
        int old = atomicAdd(&g_bdone[b], 1);
        s_flag = (old == CC - 1);
    }
    __syncthreads();
    if (!s_flag) return;
    __threadfence();

    // last block of batch b: cross-chunk reduction
    float attr = 0.f;
    if (tid < KK) {
        int   cnt = 0;
        float seg = 0.f;
        #pragma unroll
        for (int cc = 0; cc < CC; cc++) { cnt += g_cntc[b][cc][tid]; seg += g_segc[b][cc][tid]; }
        attr = (s_gfirst[tid] < NN && cnt > 0) ? seg / fmaxf((float)cnt, 1.f) : 0.f;
    }
    float b1 = (tid < CC) ? g_bce1c[b][tid] : 0.f;
    float b0 = (tid < CC) ? g_bce0c[b][tid] : 0.f;

    #pragma unroll
    for (int off = 16; off; off >>= 1) {
        attr += __shfl_down_sync(0xffffffffu, attr, off);
        b1   += __shfl_down_sync(0xffffffffu, b1,   off);
        b0   += __shfl_down_sync(0xffffffffu, b0,   off);
    }
    if (lane == 0) { s_red[0][wrp] = attr; s_red[1][wrp] = b1; s_red[2][wrp] = b0; }
    __syncthreads();
    if (tid == 0) {
        float A = 0.f, S1 = 0.f, S0 = 0.f;
        #pragma unroll
        for (int w = 0; w < CHUNK / 32; w++) { A += s_red[0][w]; S1 += s_red[1][w]; S0 += s_red[2][w]; }
        int   P   = atomicAdd(&g_pos[b], 0);      // stable: all chunks done
        float pos = (float)P;
        float neg = (float)NN - pos;
        int valid = (pos >= 1.f) && (neg >= 1.f);
        float pw  = neg / (pos + 1e-6f);
        float bce = (pw * S1 + S0) / (float)NN;
        g_partial[b] = bce + A;
        g_validb[b]  = valid;
    }
}

// ============ kernel 2: tiled symmetric repulsion + fused finalize ============
__global__ void __launch_bounds__(TILE) k_rep(float* __restrict__ out)
{
    const int ti = blockIdx.x;
    const int tj = blockIdx.y;
    const int b  = blockIdx.z;
    const int t  = threadIdx.x;
    const int P  = g_pos[b];
    const int i0 = ti * TILE;
    const int j0 = tj * TILE;

    __shared__ float sE[TILE][DD];
    __shared__ float sQ[TILE];
    __shared__ float sred[TILE];

    const bool active = (tj >= ti) && (i0 < P) && (j0 < P);   // block-uniform
    if (active) {
        const int jn = min(TILE, P - j0);
        for (int q = t; q < jn * 2; q += TILE) {
            int r = q >> 1, p = (q & 1) * 4;
            *(float4*)&sE[r][p] = *(const float4*)&g_cp_emb[b][j0 + r][p];
        }
        if (t < jn) sQ[t] = g_cp_sq2[b][j0 + t];
        __syncthreads();

        const int  gi = i0 + t;
        const bool iv = gi < P;
        float e0=0,e1=0,e2=0,e3=0,e4=0,e5=0,e6=0,e7=0, nq=0.f;
        if (iv) {
            float4 a = *(const float4*)&g_cp_emb[b][gi][0];
            float4 d = *(const float4*)&g_cp_emb[b][gi][4];
            e0=a.x; e1=a.y; e2=a.z; e3=a.w;
            e4=d.x; e5=d.y; e6=d.z; e7=d.w;
            nq = -g_cp_sq2[b][gi];
        }

        float acc = 0.f;
        if (ti != tj && jn == TILE) {
            if (iv) {
                #pragma unroll 4
                for (int jj = 0; jj < TILE; jj++) {
                    float4 a = *(const float4*)&sE[jj][0];
                    float4 d = *(const float4*)&sE[jj][4];
                    float dot = e0*a.x + e1*a.y + e2*a.z + e3*a.w
                              + e4*d.x + e5*d.y + e6*d.z + e7*d.w;
                    float arg = fminf(fmaf(dot, TWO_LOG2E, nq - sQ[jj]), 0.f);
                    acc += ex2f(arg);
                }
            }
        } else {
            #pragma unroll 4
            for (int jj = 0; jj < jn; jj++) {
                float4 a = *(const float4*)&sE[jj][0];
                float4 d = *(const float4*)&sE[jj][4];
                float dot = e0*a.x + e1*a.y + e2*a.z + e3*a.w
                          + e4*d.x + e5*d.y + e6*d.z + e7*d.w;
                float arg = fminf(fmaf(dot, TWO_LOG2E, nq - sQ[jj]), 0.f);
                float ex  = ex2f(arg);
                acc += (iv && (j0 + jj) > gi) ? ex : 0.f;   // strict upper triangle
            }
        }

        sred[t] = acc;
        __syncthreads();
        #pragma unroll
        for (int off = TILE / 2; off > 0; off >>= 1) {
            if (t < off) sred[t] += sred[t + off];
            __syncthreads();
        }
        if (t == 0) atomicAdd(&g_repsum[b], sred[0]);
    }

    // ---------------- completion-elected finalize ----------------
    __threadfence();
    if (t == 0) {
        int old = atomicAdd(&g_done, 1);
        if (old == TOTAL_REP_BLOCKS - 1) {
            __threadfence();
            float ts = 0.f, cnt = 0.f;
            #pragma unroll
            for (int bb = 0; bb < BB; bb++) {
                int   Pb  = atomicAdd(&g_pos[bb], 0);
                float S   = atomicAdd(&g_repsum[bb], 0.f);
                float pos = (float)Pb;
                float rep_sum = pos + 2.f * S;            // diagonal = pos exactly
                float repl = (pos > 1.f) ? rep_sum / fmaxf(pos * pos, 1.f) : 0.f;
                float tot  = g_partial[bb] + repl;
                if (g_validb[bb]) { ts += tot; cnt += 1.f; }
            }
            out[0] = (cnt > 0.f) ? ts / fmaxf(cnt, 1.f) : 0.f;
            // reset all counters/accumulators for the next graph replay
            g_done = 0;
            #pragma unroll
            for (int bb = 0; bb < BB; bb++) {
                g_pos[bb]    = 0;
                g_repsum[bb] = 0.f;
                g_arrive[bb] = 0;
                g_bdone[bb]  = 0;
            }
        }
    }
}

// ================= launch =================
extern "C" void kernel_launch(void* const* d_in, const int* in_sizes, int n_in,
                              void* d_out, int out_size)
{
    const float* beta  = (const float*)d_in[0];
    const float* embed = (const float*)d_in[1];
    const int*   sid   = (const int*)  d_in[2];
    const int*   iscp  = (const int*)  d_in[3];
    float* out = (float*)d_out;

    dim3 g1(CC, BB);
    k_fused<<<g1, CHUNK>>>(beta, embed, sid, iscp);
    dim3 g2(TMAX, TMAX, BB);
    k_rep<<<g2, TILE>>>(out);
}

// round 4
// speedup vs baseline: 1.0714x; 1.0714x over previous
#include <cuda_runtime.h>
#include <math.h>

#define BB 4
#define NN 4096
#define DD 8
#define KK 64              /* instance ids */
#define CC 16              /* chunks per batch */
#define CHUNK 256          /* elements per chunk == threads (pass1/pass2) */
#define TILE 128           /* j-tile + threads in k_rep */
#define ITILE 256          /* i-rows per rep block (2 per thread) */
#define GI (NN / ITILE)    /* 16 */
#define TMAX (NN / TILE)   /* 32 */

#define LOG2E  1.4426950408889634f
#define SCALE  1.6986436f          /* sqrt(2*log2(e)) */

typedef unsigned long long ull;

// ---------------- scratch (no allocations allowed) ----------------
__device__ float g_cp_emb[BB][NN][DD];   // compacted CP embeddings, pre-scaled by SCALE
__device__ float g_cp_sq2[BB][NN];       // compacted |e_raw|^2 * log2(e)
__device__ int   g_pos   [BB];           // compaction ticket -> pos (reset by k_final)
__device__ int   g_cntc  [BB][CC][KK];
__device__ int   g_firstc[BB][CC][KK];
__device__ float g_segc  [BB][CC][KK];
__device__ float g_bce1c [BB][CC];
__device__ float g_bce0c [BB][CC];
__device__ float g_partial[BB];          // bce + attraction
__device__ int   g_validb [BB];
__device__ float g_repsum [BB];          // accumulated by k_rep blocks (reset by k_final)
__device__ int   g_bdone  [BB];          // pass2 election counters (reset by k_final)

__device__ __forceinline__ float ex2f(float x) {
    float r; asm("ex2.approx.ftz.f32 %0, %1;" : "=f"(r) : "f"(x)); return r;
}
__device__ __forceinline__ float softplus_f(float x) {
    return fmaxf(x, 0.f) + log1pf(expf(-fabsf(x)));
}
__device__ __forceinline__ ull ffma2(ull a, ull b, ull c) {
    ull d; asm("fma.rn.f32x2 %0, %1, %2, %3;" : "=l"(d) : "l"(a), "l"(b), "l"(c));
    return d;
}
__device__ __forceinline__ float f2sum(ull v) {
    float lo, hi;
    asm("mov.b64 {%0, %1}, %2;" : "=f"(lo), "=f"(hi) : "l"(v));
    return lo + hi;
}

// ============ kernel 1: counts, first-CP, BCE partials, scaled CP compaction ============
__global__ void __launch_bounds__(CHUNK) k_pass1(const float* __restrict__ beta,
                                                 const float* __restrict__ embed,
                                                 const int*   __restrict__ sid,
                                                 const int*   __restrict__ iscp)
{
    const int c   = blockIdx.x;
    const int b   = blockIdx.y;
    const int tid = threadIdx.x;
    const int i   = c * CHUNK + tid;
    const int g   = b * NN + i;
    const int lane = tid & 31;

    __shared__ int   s_cnt[KK];
    __shared__ int   s_first[KK];
    __shared__ float s_w1[CHUNK / 32];
    __shared__ float s_w0[CHUNK / 32];

    if (tid < KK) { s_cnt[tid] = 0; s_first[tid] = NN; }
    __syncthreads();

    const int   s  = sid[g];
    const int   cp = iscp[g];
    const float bt = beta[g];

    atomicAdd(&s_cnt[s], 1);
    float l1 = 0.f, l0 = 0.f;
    if (cp == 1) { atomicMin(&s_first[s], i); l1 = softplus_f(-bt); }
    else         { l0 = softplus_f(bt); }

    // warp-aggregated compaction ticket (integer -> exact pos count)
    const unsigned bal = __ballot_sync(0xffffffffu, cp == 1);
    if (bal) {
        const int nw = __popc(bal);
        const int leader = __ffs(bal) - 1;
        int base = 0;
        if (lane == leader) base = atomicAdd(&g_pos[b], nw);
        base = __shfl_sync(0xffffffffu, base, leader);
        if (cp == 1) {
            const int w = base + __popc(bal & ((1u << lane) - 1u));
            const float4* e = (const float4*)&embed[(size_t)g * DD];
            float4 a = e[0], d = e[1];
            float sq = a.x*a.x + a.y*a.y + a.z*a.z + a.w*a.w
                     + d.x*d.x + d.y*d.y + d.z*d.z + d.w*d.w;
            float4 as = make_float4(a.x*SCALE, a.y*SCALE, a.z*SCALE, a.w*SCALE);
            float4 ds = make_float4(d.x*SCALE, d.y*SCALE, d.z*SCALE, d.w*SCALE);
            *(float4*)&g_cp_emb[b][w][0] = as;
            *(float4*)&g_cp_emb[b][w][4] = ds;
            g_cp_sq2[b][w] = sq * LOG2E;
        }
    }

    #pragma unroll
    for (int off = 16; off; off >>= 1) {
        l1 += __shfl_down_sync(0xffffffffu, l1, off);
        l0 += __shfl_down_sync(0xffffffffu, l0, off);
    }
    if (lane == 0) { s_w1[tid >> 5] = l1; s_w0[tid >> 5] = l0; }
    __syncthreads();

    if (tid < KK) { g_cntc[b][c][tid] = s_cnt[tid]; g_firstc[b][c][tid] = s_first[tid]; }
    if (tid == 0) {
        float S1 = 0.f, S0 = 0.f;
        #pragma unroll
        for (int w = 0; w < CHUNK / 32; w++) { S1 += s_w1[w]; S0 += s_w0[w]; }
        g_bce1c[b][c] = S1;
        g_bce0c[b][c] = S0;
    }
}

// ============ kernel 2: attraction segment sums + per-batch elected finalize ============
__global__ void __launch_bounds__(CHUNK) k_pass2(const float* __restrict__ embed,
                                                 const int*   __restrict__ sid)
{
    const int c   = blockIdx.x;
    const int b   = blockIdx.y;
    const int tid = threadIdx.x;
    const int lane = tid & 31;
    const int wrp  = tid >> 5;

    __shared__ int   s_gfirst[KK];
    __shared__ float s_cpe[KK][DD];
    __shared__ float s_seg[KK];
    __shared__ float s_red[3][CHUNK / 32];
    __shared__ int   s_flag;

    if (tid < KK) {
        int f = NN;
        #pragma unroll
        for (int cc = 0; cc < CC; cc++) f = min(f, g_firstc[b][cc][tid]);
        s_gfirst[tid] = f;
        s_seg[tid]    = 0.f;
        if (f < NN) {
            const float4* e = (const float4*)&embed[((size_t)b * NN + f) * DD];
            *(float4*)&s_cpe[tid][0] = e[0];
            *(float4*)&s_cpe[tid][4] = e[1];
        }
    }
    __syncthreads();

    const int i = c * CHUNK + tid;
    const int g = b * NN + i;
    const int s = sid[g];
    if (s_gfirst[s] < NN) {
        const float4* e = (const float4*)&embed[(size_t)g * DD];
        float4 a = e[0], d = e[1];
        float x0 = a.x - s_cpe[s][0], x1 = a.y - s_cpe[s][1];
        float x2 = a.z - s_cpe[s][2], x3 = a.w - s_cpe[s][3];
        float x4 = d.x - s_cpe[s][4], x5 = d.y - s_cpe[s][5];
        float x6 = d.z - s_cpe[s][6], x7 = d.w - s_cpe[s][7];
        float d2 = x0*x0 + x1*x1 + x2*x2 + x3*x3 + x4*x4 + x5*x5 + x6*x6 + x7*x7;
        atomicAdd(&s_seg[s], d2);
    }
    __syncthreads();
    if (tid < KK) g_segc[b][c][tid] = s_seg[tid];

    // ---- per-batch election: last of CC blocks reduces everything ----
    __threadfence();
    if (tid == 0) {
        int old = atomicAdd(&g_bdone[b], 1);
        s_flag = (old == CC - 1);
    }
    __syncthreads();
    if (!s_flag) return;
    __threadfence();

    float attr = 0.f;
    if (tid < KK) {
        int   cnt = 0;
        float seg = 0.f;
        #pragma unroll
        for (int cc = 0; cc < CC; cc++) { cnt += g_cntc[b][cc][tid]; seg += g_segc[b][cc][tid]; }
        attr = (s_gfirst[tid] < NN && cnt > 0) ? seg / fmaxf((float)cnt, 1.f) : 0.f;
    }
    float b1 = (tid < CC) ? g_bce1c[b][tid] : 0.f;
    float b0 = (tid < CC) ? g_bce0c[b][tid] : 0.f;

    #pragma unroll
    for (int off = 16; off; off >>= 1) {
        attr += __shfl_down_sync(0xffffffffu, attr, off);
        b1   += __shfl_down_sync(0xffffffffu, b1,   off);
        b0   += __shfl_down_sync(0xffffffffu, b0,   off);
    }
    if (lane == 0) { s_red[0][wrp] = attr; s_red[1][wrp] = b1; s_red[2][wrp] = b0; }
    __syncthreads();
    if (tid == 0) {
        float A = 0.f, S1 = 0.f, S0 = 0.f;
        #pragma unroll
        for (int w = 0; w < CHUNK / 32; w++) { A += s_red[0][w]; S1 += s_red[1][w]; S0 += s_red[2][w]; }
        int   P   = g_pos[b];          // stable since k_pass1 finished
        float pos = (float)P;
        float neg = (float)NN - pos;
        int   valid = (pos >= 1.f) && (neg >= 1.f);
        float pw  = neg / (pos + 1e-6f);
        float bce = (pw * S1 + S0) / (float)NN;
        g_partial[b] = bce + A;
        g_validb[b]  = valid;
    }
}

// ============ kernel 3: tiled symmetric repulsion (2 rows/thread, f32x2 math) ============
__global__ void __launch_bounds__(TILE) k_rep()
{
    const int ti = blockIdx.x;              // 0..GI-1   (i-tiles of 256)
    const int tj = blockIdx.y;              // 0..TMAX-1 (j-tiles of 128)
    if (tj < 2 * ti) return;                // no j > i possible
    const int b  = blockIdx.z;
    const int P  = g_pos[b];
    const int i0 = ti * ITILE;
    const int j0 = tj * TILE;
    if (i0 >= P || j0 >= P) return;

    __shared__ float sE[TILE][DD];
    __shared__ float sQ[TILE];
    __shared__ float sred[TILE];

    const int t  = threadIdx.x;
    const int jn = min(TILE, P - j0);

    for (int q = t; q < jn * 2; q += TILE) {
        int r = q >> 1, p = (q & 1) * 4;
        *(float4*)&sE[r][p] = *(const float4*)&g_cp_emb[b][j0 + r][p];
    }
    if (t < jn) sQ[t] = g_cp_sq2[b][j0 + t];
    __syncthreads();

    const int  gi0 = i0 + t;
    const int  gi1 = gi0 + TILE;
    const bool iv0 = gi0 < P;
    const bool iv1 = gi1 < P;

    ull a0_01 = 0, a0_23 = 0, a0_45 = 0, a0_67 = 0;
    ull a1_01 = 0, a1_23 = 0, a1_45 = 0, a1_67 = 0;
    float nq0 = -3.0e38f, nq1 = -3.0e38f;   // invalid rows -> arg ~ -inf -> ex2 = 0
    if (iv0) {
        const ulonglong2* r = (const ulonglong2*)&g_cp_emb[b][gi0][0];
        ulonglong2 u = r[0], v = r[1];
        a0_01 = u.x; a0_23 = u.y; a0_45 = v.x; a0_67 = v.y;
        nq0 = -g_cp_sq2[b][gi0];
    }
    if (iv1) {
        const ulonglong2* r = (const ulonglong2*)&g_cp_emb[b][gi1][0];
        ulonglong2 u = r[0], v = r[1];
        a1_01 = u.x; a1_23 = u.y; a1_45 = v.x; a1_67 = v.y;
        nq1 = -g_cp_sq2[b][gi1];
    }

    float acc0 = 0.f, acc1 = 0.f;
    const bool clean = (tj >= 2 * ti + 2) && (jn == TILE);  // all j > all i
    if (clean) {
        #pragma unroll 4
        for (int jj = 0; jj < TILE; jj++) {
            const ull* jr = (const ull*)sE[jj];
            ull j01 = jr[0], j23 = jr[1], j45 = jr[2], j67 = jr[3];
            float sqj = sQ[jj];
            ull c0 = ffma2(a0_01, j01, ffma2(a0_23, j23, ffma2(a0_45, j45, ffma2(a0_67, j67, 0ULL))));
            ull c1 = ffma2(a1_01, j01, ffma2(a1_23, j23, ffma2(a1_45, j45, ffma2(a1_67, j67, 0ULL))));
            float arg0 = fminf(f2sum(c0) + (nq0 - sqj), 0.f);
            float arg1 = fminf(f2sum(c1) + (nq1 - sqj), 0.f);
            acc0 += ex2f(arg0);
            acc1 += ex2f(arg1);
        }
    } else {
        #pragma unroll 4
        for (int jj = 0; jj < jn; jj++) {
            const ull* jr = (const ull*)sE[jj];
            ull j01 = jr[0], j23 = jr[1], j45 = jr[2], j67 = jr[3];
            float sqj = sQ[jj];
            ull c0 = ffma2(a0_01, j01, ffma2(a0_23, j23, ffma2(a0_45, j45, ffma2(a0_67, j67, 0ULL))));
            ull c1 = ffma2(a1_01, j01, ffma2(a1_23, j23, ffma2(a1_45, j45, ffma2(a1_67, j67, 0ULL))));
            float ex0 = ex2f(fminf(f2sum(c0) + (nq0 - sqj), 0.f));
            float ex1 = ex2f(fminf(f2sum(c1) + (nq1 - sqj), 0.f));
            int jg = j0 + jj;
            acc0 += (jg > gi0) ? ex0 : 0.f;   // strict upper triangle
            acc1 += (jg > gi1) ? ex1 : 0.f;
        }
    }

    sred[t] = acc0 + acc1;
    __syncthreads();
    #pragma unroll
    for (int off = TILE / 2; off > 0; off >>= 1) {
        if (t < off) sred[t] += sred[t + off];
        __syncthreads();
    }
    if (t == 0) atomicAdd(&g_repsum[b], sred[0]);
}

// ============ kernel 4: combine 16 scalars + reset counters ============
__global__ void k_final(float* __restrict__ out)
{
    if (threadIdx.x == 0) {
        float ts = 0.f, cnt = 0.f;
        #pragma unroll
        for (int b = 0; b < BB; b++) {
            float pos = (float)g_pos[b];
            float S   = g_repsum[b];
            float rep_sum = pos + 2.f * S;              // diagonal = pos exactly
            float rep = (pos > 1.f) ? rep_sum / fmaxf(pos * pos, 1.f) : 0.f;
            float tot = g_partial[b] + rep;
            if (g_validb[b]) { ts += tot; cnt += 1.f; }
        }
        out[0] = (cnt > 0.f) ? ts / fmaxf(cnt, 1.f) : 0.f;
    }
    // reset for next graph replay
    if (threadIdx.x < BB) {
        g_pos   [threadIdx.x] = 0;
        g_repsum[threadIdx.x] = 0.f;
        g_bdone [threadIdx.x] = 0;
    }
}

// ================= launch =================
extern "C" void kernel_launch(void* const* d_in, const int* in_sizes, int n_in,
                              void* d_out, int out_size)
{
    const float* beta  = (const float*)d_in[0];
    const float* embed = (const float*)d_in[1];
    const int*   sid   = (const int*)  d_in[2];
    const int*   iscp  = (const int*)  d_in[3];
    float* out = (float*)d_out;

    dim3 g1(CC, BB);
    k_pass1<<<g1, CHUNK>>>(beta, embed, sid, iscp);
    k_pass2<<<g1, CHUNK>>>(embed, sid);
    dim3 g2(GI, TMAX, BB);
    k_rep<<<g2, TILE>>>();
    k_final<<<1, 32>>>(out);
}

// round 5
// speedup vs baseline: 1.2436x; 1.1607x over previous
#include <cuda_runtime.h>
#include <math.h>

#define BB 4
#define NN 4096
#define DD 8
#define KK 64               /* instance ids */
#define CC1 16              /* pass1 chunks per batch (256 thr) */
#define CH1 256
#define TILE 128            /* j-tile + threads in K2 */
#define ITILE 256           /* i-rows per rep block */
#define GI (NN / ITILE)     /* 16 */
#define TMAX (NN / TILE)    /* 32 */
#define CC2 32              /* attraction chunks per batch (128 thr, inside K2) */

#define LOG2E  1.4426950408889634f
#define SCALE  1.6986436f   /* sqrt(2*log2(e)) */

typedef unsigned long long ull;

// ---------------- scratch (no allocations allowed) ----------------
__device__ float g_cp_emb[BB][NN][DD];    // compacted CP embeddings, pre-scaled by SCALE
__device__ float g_cp_sq2[BB][NN];        // compacted |e_raw|^2 * log2(e)
__device__ int   g_pos   [BB];            // compaction ticket -> pos
__device__ int   g_cntc  [BB][CC1][KK];
__device__ int   g_firstc[BB][CC1][KK];
__device__ float g_bce1c [BB][CC1];
__device__ float g_bce0c [BB][CC1];
__device__ float g_segc  [BB][CC2][KK];   // attraction d2 sums (written in K2)
__device__ float g_repsum[BB];
__device__ float g_tot   [BB];
__device__ int   g_validb[BB];
__device__ int   g_bdone [BB];            // per-batch election counters
__device__ int   g_alldone;               // 4-wide final election

__device__ __forceinline__ float ex2f(float x) {
    float r; asm("ex2.approx.ftz.f32 %0, %1;" : "=f"(r) : "f"(x)); return r;
}
__device__ __forceinline__ float softplus_f(float x) {
    return fmaxf(x, 0.f) + log1pf(expf(-fabsf(x)));
}
__device__ __forceinline__ ull ffma2(ull a, ull b, ull c) {
    ull d; asm("fma.rn.f32x2 %0, %1, %2, %3;" : "=l"(d) : "l"(a), "l"(b), "l"(c));
    return d;
}
__device__ __forceinline__ float f2sum(ull v) {
    float lo, hi;
    asm("mov.b64 {%0, %1}, %2;" : "=f"(lo), "=f"(hi) : "l"(v));
    return lo + hi;
}

// ============ kernel 1: counts, first-CP, BCE partials, scaled CP compaction ============
__global__ void __launch_bounds__(CH1) k_pass1(const float* __restrict__ beta,
                                               const float* __restrict__ embed,
                                               const int*   __restrict__ sid,
                                               const int*   __restrict__ iscp)
{
    const int c   = blockIdx.x;
    const int b   = blockIdx.y;
    const int tid = threadIdx.x;
    const int i   = c * CH1 + tid;
    const int g   = b * NN + i;
    const int lane = tid & 31;

    __shared__ int   s_cnt[KK];
    __shared__ int   s_first[KK];
    __shared__ float s_w1[CH1 / 32];
    __shared__ float s_w0[CH1 / 32];

    if (tid < KK) { s_cnt[tid] = 0; s_first[tid] = NN; }
    __syncthreads();

    const int   s  = sid[g];
    const int   cp = iscp[g];
    const float bt = beta[g];

    atomicAdd(&s_cnt[s], 1);
    float l1 = 0.f, l0 = 0.f;
    if (cp == 1) { atomicMin(&s_first[s], i); l1 = softplus_f(-bt); }
    else         { l0 = softplus_f(bt); }

    const unsigned bal = __ballot_sync(0xffffffffu, cp == 1);
    if (bal) {
        const int nw = __popc(bal);
        const int leader = __ffs(bal) - 1;
        int base = 0;
        if (lane == leader) base = atomicAdd(&g_pos[b], nw);
        base = __shfl_sync(0xffffffffu, base, leader);
        if (cp == 1) {
            const int w = base + __popc(bal & ((1u << lane) - 1u));
            const float4* e = (const float4*)&embed[(size_t)g * DD];
            float4 a = e[0], d = e[1];
            float sq = a.x*a.x + a.y*a.y + a.z*a.z + a.w*a.w
                     + d.x*d.x + d.y*d.y + d.z*d.z + d.w*d.w;
            float4 as = make_float4(a.x*SCALE, a.y*SCALE, a.z*SCALE, a.w*SCALE);
            float4 ds = make_float4(d.x*SCALE, d.y*SCALE, d.z*SCALE, d.w*SCALE);
            *(float4*)&g_cp_emb[b][w][0] = as;
            *(float4*)&g_cp_emb[b][w][4] = ds;
            g_cp_sq2[b][w] = sq * LOG2E;
        }
    }

    #pragma unroll
    for (int off = 16; off; off >>= 1) {
        l1 += __shfl_down_sync(0xffffffffu, l1, off);
        l0 += __shfl_down_sync(0xffffffffu, l0, off);
    }
    if (lane == 0) { s_w1[tid >> 5] = l1; s_w0[tid >> 5] = l0; }
    __syncthreads();

    if (tid < KK) { g_cntc[b][c][tid] = s_cnt[tid]; g_firstc[b][c][tid] = s_first[tid]; }
    if (tid == 0) {
        float S1 = 0.f, S0 = 0.f;
        #pragma unroll
        for (int w = 0; w < CH1 / 32; w++) { S1 += s_w1[w]; S0 += s_w0[w]; }
        g_bce1c[b][c] = S1;
        g_bce0c[b][c] = S0;
    }
}

// exact number of rep-active blocks for a batch with P compacted points
__device__ __forceinline__ int nact_of(int P) {
    int jt = min(TMAX, (P + TILE - 1) / TILE);
    int it = min(GI,   (P + ITILE - 1) / ITILE);
    int n = 0;
    #pragma unroll
    for (int ti = 0; ti < GI; ti++)
        if (ti < it) n += max(0, jt - 2 * ti);
    return n;
}

// ============ kernel 2: repulsion + attraction (spare blocks) + device finalize ============
__global__ void __launch_bounds__(TILE) k_rep_fused(const float* __restrict__ embed,
                                                    const int*   __restrict__ sid,
                                                    float* __restrict__ out)
{
    const int ti = blockIdx.x;              // 0..GI-1
    const int tj = blockIdx.y;              // 0..TMAX-1
    const int b  = blockIdx.z;
    const int t  = threadIdx.x;
    const int lane = t & 31;
    const int P  = g_pos[b];
    const int i0 = ti * ITILE;
    const int j0 = tj * TILE;

    const bool rep_active = (tj >= 2 * ti) && (i0 < P) && (j0 < P);
    const bool is_attr    = (ti >= 8) && (tj < 4);      // 32 fixed lower-triangle blocks

    __shared__ float sE[TILE][DD];
    __shared__ float sQ[TILE];
    __shared__ float sred[TILE];
    __shared__ int   s_gfirst[KK];
    __shared__ float s_cpe[KK][DD];
    __shared__ float s_seg[KK];
    __shared__ int   s_role;

    if (rep_active) {
        const int jn = min(TILE, P - j0);
        for (int q = t; q < jn * 2; q += TILE) {
            int r = q >> 1, p = (q & 1) * 4;
            *(float4*)&sE[r][p] = *(const float4*)&g_cp_emb[b][j0 + r][p];
        }
        if (t < jn) sQ[t] = g_cp_sq2[b][j0 + t];
        __syncthreads();

        const int  gi0 = i0 + t;
        const int  gi1 = gi0 + TILE;
        ull a0_01 = 0, a0_23 = 0, a0_45 = 0, a0_67 = 0;
        ull a1_01 = 0, a1_23 = 0, a1_45 = 0, a1_67 = 0;
        float nq0 = -3.0e38f, nq1 = -3.0e38f;
        if (gi0 < P) {
            const ulonglong2* r = (const ulonglong2*)&g_cp_emb[b][gi0][0];
            ulonglong2 u = r[0], v = r[1];
            a0_01 = u.x; a0_23 = u.y; a0_45 = v.x; a0_67 = v.y;
            nq0 = -g_cp_sq2[b][gi0];
        }
        if (gi1 < P) {
            const ulonglong2* r = (const ulonglong2*)&g_cp_emb[b][gi1][0];
            ulonglong2 u = r[0], v = r[1];
            a1_01 = u.x; a1_23 = u.y; a1_45 = v.x; a1_67 = v.y;
            nq1 = -g_cp_sq2[b][gi1];
        }

        float acc0 = 0.f, acc1 = 0.f;
        const bool clean = (tj >= 2 * ti + 2) && (jn == TILE);
        if (clean) {
            #pragma unroll 4
            for (int jj = 0; jj < TILE; jj++) {
                const ull* jr = (const ull*)sE[jj];
                ull j01 = jr[0], j23 = jr[1], j45 = jr[2], j67 = jr[3];
                float sqj = sQ[jj];
                ull c0 = ffma2(a0_01, j01, ffma2(a0_23, j23, ffma2(a0_45, j45, ffma2(a0_67, j67, 0ULL))));
                ull c1 = ffma2(a1_01, j01, ffma2(a1_23, j23, ffma2(a1_45, j45, ffma2(a1_67, j67, 0ULL))));
                acc0 += ex2f(fminf(f2sum(c0) + (nq0 - sqj), 0.f));
                acc1 += ex2f(fminf(f2sum(c1) + (nq1 - sqj), 0.f));
            }
        } else {
            #pragma unroll 4
            for (int jj = 0; jj < jn; jj++) {
                const ull* jr = (const ull*)sE[jj];
                ull j01 = jr[0], j23 = jr[1], j45 = jr[2], j67 = jr[3];
                float sqj = sQ[jj];
                ull c0 = ffma2(a0_01, j01, ffma2(a0_23, j23, ffma2(a0_45, j45, ffma2(a0_67, j67, 0ULL))));
                ull c1 = ffma2(a1_01, j01, ffma2(a1_23, j23, ffma2(a1_45, j45, ffma2(a1_67, j67, 0ULL))));
                float ex0 = ex2f(fminf(f2sum(c0) + (nq0 - sqj), 0.f));
                float ex1 = ex2f(fminf(f2sum(c1) + (nq1 - sqj), 0.f));
                int jg = j0 + jj;
                acc0 += (jg > gi0) ? ex0 : 0.f;
                acc1 += (jg > gi1) ? ex1 : 0.f;
            }
        }

        sred[t] = acc0 + acc1;
        __syncthreads();
        #pragma unroll
        for (int off = TILE / 2; off > 0; off >>= 1) {
            if (t < off) sred[t] += sred[t + off];
            __syncthreads();
        }
        if (t == 0) atomicAdd(&g_repsum[b], sred[0]);
    }
    else if (is_attr) {
        const int c = (ti - 8) * 4 + tj;    // 0..31
        if (t < KK) {
            int f = NN;
            #pragma unroll
            for (int cc = 0; cc < CC1; cc++) f = min(f, g_firstc[b][cc][t]);
            s_gfirst[t] = f;
            s_seg[t]    = 0.f;
            if (f < NN) {
                const float4* e = (const float4*)&embed[((size_t)b * NN + f) * DD];
                *(float4*)&s_cpe[t][0] = e[0];
                *(float4*)&s_cpe[t][4] = e[1];
            }
        }
        __syncthreads();

        const int i = c * TILE + t;
        const int g = b * NN + i;
        const int s = sid[g];
        if (s_gfirst[s] < NN) {
            const float4* e = (const float4*)&embed[(size_t)g * DD];
            float4 a = e[0], d = e[1];
            float x0 = a.x - s_cpe[s][0], x1 = a.y - s_cpe[s][1];
            float x2 = a.z - s_cpe[s][2], x3 = a.w - s_cpe[s][3];
            float x4 = d.x - s_cpe[s][4], x5 = d.y - s_cpe[s][5];
            float x6 = d.z - s_cpe[s][6], x7 = d.w - s_cpe[s][7];
            float d2 = x0*x0 + x1*x1 + x2*x2 + x3*x3 + x4*x4 + x5*x5 + x6*x6 + x7*x7;
            atomicAdd(&s_seg[s], d2);
        }
        __syncthreads();
        if (t < KK) g_segc[b][c][t] = s_seg[t];
    }
    else {
        return;     // pure filler block: no counter participation
    }

    // ---------------- per-batch election ----------------
    __threadfence();
    if (t == 0) {
        const int target = nact_of(P) + CC2;
        int old = atomicAdd(&g_bdone[b], 1);
        s_role = (old == target - 1);
    }
    __syncthreads();
    if (!s_role) return;
    __threadfence();

    // ======== batch finalize (one block per batch) ========
    float attr = 0.f;
    if (t < KK) {
        int f = NN, cnt = 0;
        #pragma unroll
        for (int cc = 0; cc < CC1; cc++) {
            f   = min(f, g_firstc[b][cc][t]);
            cnt += g_cntc[b][cc][t];
        }
        float seg = 0.f;
        #pragma unroll
        for (int cc = 0; cc < CC2; cc++) seg += g_segc[b][cc][t];
        attr = (f < NN && cnt > 0) ? seg / fmaxf((float)cnt, 1.f) : 0.f;
    }
    float b1 = (t < CC1) ? g_bce1c[b][t] : 0.f;
    float b0 = (t < CC1) ? g_bce0c[b][t] : 0.f;

    #pragma unroll
    for (int off = 16; off; off >>= 1) {
        attr += __shfl_down_sync(0xffffffffu, attr, off);
        b1   += __shfl_down_sync(0xffffffffu, b1,   off);
        b0   += __shfl_down_sync(0xffffffffu, b0,   off);
    }
    // attr lives in warps 0-1 (t<64); b1/b0 only warp 0
    if (lane == 0) sred[t >> 5] = attr;
    __syncthreads();
    if (t == 0) {
        float A   = sred[0] + sred[1];
        float pos = (float)P;
        float neg = (float)NN - pos;
        int   valid = (pos >= 1.f) && (neg >= 1.f);
        float pw  = neg / (pos + 1e-6f);
        float bce = (pw * b1 + b0) / (float)NN;
        float S   = atomicAdd(&g_repsum[b], 0.f);
        float rep_sum = pos + 2.f * S;                    // diagonal = pos exactly
        float rep = (pos > 1.f) ? rep_sum / fmaxf(pos * pos, 1.f) : 0.f;
        g_tot[b]    = bce + A + rep;
        g_validb[b] = valid;
        __threadfence();
        int old = atomicAdd(&g_alldone, 1);
        s_role = (old == BB - 1) ? 2 : 0;
    }
    __syncthreads();
    if (s_role != 2) return;

    // ======== global finalize (exactly one block) ========
    if (t == 0) {
        __threadfence();
        float ts = 0.f, cnt = 0.f;
        #pragma unroll
        for (int bb = 0; bb < BB; bb++) {
            if (g_validb[bb]) { ts += g_tot[bb]; cnt += 1.f; }
        }
        out[0] = (cnt > 0.f) ? ts / fmaxf(cnt, 1.f) : 0.f;
        // reset for next graph replay
        g_alldone = 0;
        #pragma unroll
        for (int bb = 0; bb < BB; bb++) {
            g_pos[bb]    = 0;
            g_repsum[bb] = 0.f;
            g_bdone[bb]  = 0;
        }
    }
}

// ================= launch =================
extern "C" void kernel_launch(void* const* d_in, const int* in_sizes, int n_in,
                              void* d_out, int out_size)
{
    const float* beta  = (const float*)d_in[0];
    const float* embed = (const float*)d_in[1];
    const int*   sid   = (const int*)  d_in[2];
    const int*   iscp  = (const int*)  d_in[3];
    float* out = (float*)d_out;

    dim3 g1(CC1, BB);
    k_pass1<<<g1, CH1>>>(beta, embed, sid, iscp);
    dim3 g2(GI, TMAX, BB);
    k_rep_fused<<<g2, TILE>>>(embed, sid, out);
}

// round 6
// speedup vs baseline: 1.5931x; 1.2810x over previous
#include <cuda_runtime.h>
#include <math.h>

#define BB 4
#define NN 4096
#define DD 8
#define KK 64               /* instance ids */
#define CC1 16              /* pass1 chunks per batch */
#define CH1 256             /* pass1 threads */
#define TILE 128            /* rep tile edge + K2 threads */
#define TMAX (NN / TILE)    /* 32 */
#define TA   128            /* attraction tasks: 4 batches x 32 chunks of 128 */
#define G2   1024           /* K2 grid size */

#define LOG2E  1.4426950408889634f
#define SCALE  1.6986436f   /* sqrt(2*log2(e)) */

typedef unsigned long long ull;

// ---------------- scratch (no allocations allowed; all zero-init valid) ----------------
__device__ float g_cp_emb[BB][NN][DD];   // compacted CP embeddings, pre-scaled by SCALE
__device__ float g_cp_sq2[BB][NN];       // compacted |e_raw|^2 * log2(e)
__device__ int   g_pos     [BB];         // compaction ticket -> pos
__device__ int   g_cnt     [BB][KK];     // per-segment counts (int atomics)
__device__ int   g_firstmax[BB][KK];     // max(NN - i) over CP hits; 0 = no CP
__device__ float g_bce1    [BB];
__device__ float g_bce0    [BB];
__device__ float g_seg     [BB][KK];     // attraction d2 sums
__device__ float g_repsum  [BB];
__device__ int   g_done;                 // K2 completion counter

__device__ __forceinline__ float ex2f(float x) {
    float r; asm("ex2.approx.ftz.f32 %0, %1;" : "=f"(r) : "f"(x)); return r;
}
__device__ __forceinline__ float softplus_f(float x) {
    return fmaxf(x, 0.f) + log1pf(expf(-fabsf(x)));
}
__device__ __forceinline__ ull ffma2(ull a, ull b, ull c) {
    ull d; asm("fma.rn.f32x2 %0, %1, %2, %3;" : "=l"(d) : "l"(a), "l"(b), "l"(c));
    return d;
}
__device__ __forceinline__ float f2sum(ull v) {
    float lo, hi;
    asm("mov.b64 {%0, %1}, %2;" : "=f"(lo), "=f"(hi) : "l"(v));
    return lo + hi;
}

// ============ kernel 1: counts, first-CP, BCE, scaled CP compaction ============
__global__ void __launch_bounds__(CH1) k_pass1(const float* __restrict__ beta,
                                               const float* __restrict__ embed,
                                               const int*   __restrict__ sid,
                                               const int*   __restrict__ iscp)
{
    const int c   = blockIdx.x;
    const int b   = blockIdx.y;
    const int tid = threadIdx.x;
    const int i   = c * CH1 + tid;
    const int g   = b * NN + i;
    const int lane = tid & 31;

    __shared__ int   s_cnt[KK];
    __shared__ int   s_first[KK];
    __shared__ float s_w1[CH1 / 32];
    __shared__ float s_w0[CH1 / 32];

    if (tid < KK) { s_cnt[tid] = 0; s_first[tid] = NN; }
    __syncthreads();

    const int   s  = sid[g];
    const int   cp = iscp[g];
    const float bt = beta[g];

    atomicAdd(&s_cnt[s], 1);
    float l1 = 0.f, l0 = 0.f;
    if (cp == 1) { atomicMin(&s_first[s], i); l1 = softplus_f(-bt); }
    else         { l0 = softplus_f(bt); }

    // warp-aggregated compaction ticket
    const unsigned bal = __ballot_sync(0xffffffffu, cp == 1);
    if (bal) {
        const int nw = __popc(bal);
        const int leader = __ffs(bal) - 1;
        int base = 0;
        if (lane == leader) base = atomicAdd(&g_pos[b], nw);
        base = __shfl_sync(0xffffffffu, base, leader);
        if (cp == 1) {
            const int w = base + __popc(bal & ((1u << lane) - 1u));
            const float4* e = (const float4*)&embed[(size_t)g * DD];
            float4 a = e[0], d = e[1];
            float sq = a.x*a.x + a.y*a.y + a.z*a.z + a.w*a.w
                     + d.x*d.x + d.y*d.y + d.z*d.z + d.w*d.w;
            float4 as = make_float4(a.x*SCALE, a.y*SCALE, a.z*SCALE, a.w*SCALE);
            float4 ds = make_float4(d.x*SCALE, d.y*SCALE, d.z*SCALE, d.w*SCALE);
            *(float4*)&g_cp_emb[b][w][0] = as;
            *(float4*)&g_cp_emb[b][w][4] = ds;
            g_cp_sq2[b][w] = sq * LOG2E;
        }
    }

    #pragma unroll
    for (int off = 16; off; off >>= 1) {
        l1 += __shfl_down_sync(0xffffffffu, l1, off);
        l0 += __shfl_down_sync(0xffffffffu, l0, off);
    }
    if (lane == 0) { s_w1[tid >> 5] = l1; s_w0[tid >> 5] = l0; }
    __syncthreads();

    if (tid < KK) {
        if (s_cnt[tid] > 0)   atomicAdd(&g_cnt[b][tid], s_cnt[tid]);
        if (s_first[tid] < NN) atomicMax(&g_firstmax[b][tid], NN - s_first[tid]);
    }
    if (tid == 0) {
        float S1 = 0.f, S0 = 0.f;
        #pragma unroll
        for (int w = 0; w < CH1 / 32; w++) { S1 += s_w1[w]; S0 += s_w0[w]; }
        atomicAdd(&g_bce1[b], S1);
        atomicAdd(&g_bce0[b], S0);
    }
}

// ============ kernel 2: task-queued attraction + repulsion + elected finalize ============
__global__ void __launch_bounds__(TILE) k_main(const float* __restrict__ embed,
                                               const int*   __restrict__ sid,
                                               float* __restrict__ out)
{
    const int t    = threadIdx.x;
    const int lane = t & 31;

    __shared__ ull   sJ[TILE][6];      // [0..1]=e0..3, [2..3]=e4..7, [4]=(-sqj, 0)
    __shared__ float sred[TILE];
    __shared__ float s_cpe[KK][DD];
    __shared__ int   s_f[KK];
    __shared__ float s_seg[KK];
    __shared__ int   s_P[BB];
    __shared__ int   s_last;

    if (t < BB) s_P[t] = g_pos[t];
    __syncthreads();

    // total task count (uniform across block)
    int total = TA;
    #pragma unroll
    for (int bb = 0; bb < BB; bb++) {
        int nt = min(TMAX, (s_P[bb] + TILE - 1) >> 7);
        total += nt * (nt + 1) / 2;
    }

    for (int task = blockIdx.x; task < total; task += G2) {
        __syncthreads();                        // protect smem reuse across tasks
        if (task < TA) {
            // ---------------- attraction chunk ----------------
            const int b = task >> 5;
            const int c = task & 31;
            if (t < KK) {
                int m = g_firstmax[b][t];
                s_f[t]   = m;
                s_seg[t] = 0.f;
                if (m > 0) {
                    int f = NN - m;
                    const float4* e = (const float4*)&embed[((size_t)b * NN + f) * DD];
                    *(float4*)&s_cpe[t][0] = e[0];
                    *(float4*)&s_cpe[t][4] = e[1];
                }
            }
            __syncthreads();

            const int g = b * NN + c * TILE + t;
            const int s = sid[g];
            if (s_f[s] > 0) {
                const float4* e = (const float4*)&embed[(size_t)g * DD];
                float4 a = e[0], d = e[1];
                float x0 = a.x - s_cpe[s][0], x1 = a.y - s_cpe[s][1];
                float x2 = a.z - s_cpe[s][2], x3 = a.w - s_cpe[s][3];
                float x4 = d.x - s_cpe[s][4], x5 = d.y - s_cpe[s][5];
                float x6 = d.z - s_cpe[s][6], x7 = d.w - s_cpe[s][7];
                float d2 = x0*x0 + x1*x1 + x2*x2 + x3*x3 + x4*x4 + x5*x5 + x6*x6 + x7*x7;
                atomicAdd(&s_seg[s], d2);
            }
            __syncthreads();
            if (t < KK && s_seg[t] != 0.f) atomicAdd(&g_seg[b][t], s_seg[t]);
        } else {
            // ---------------- repulsion tile ----------------
            int q = task - TA;
            int b = 0;
            int nt = min(TMAX, (s_P[0] + TILE - 1) >> 7);
            #pragma unroll
            for (int bb = 0; bb < BB - 1; bb++) {
                int tri = nt * (nt + 1) / 2;
                if (q >= tri) { q -= tri; b = bb + 1; nt = min(TMAX, (s_P[b] + TILE - 1) >> 7); }
            }
            int ti = 0, rem = nt;
            while (q >= rem) { q -= rem; ti++; rem--; }
            const int tj = ti + q;

            const int P  = s_P[b];
            const int i0 = ti * TILE;
            const int j0 = tj * TILE;
            const int jn = min(TILE, P - j0);

            // load j-tile into smem
            if (t < jn) {
                const float4* e = (const float4*)&g_cp_emb[b][j0 + t][0];
                *(float4*)&sJ[t][0] = e[0];
                *(float4*)&sJ[t][2] = e[1];
                float nsq = -g_cp_sq2[b][j0 + t];
                sJ[t][4] = (ull)__float_as_uint(nsq);   // hi word 0 = +0.0f
            }
            __syncthreads();

            const int gi = i0 + t;
            ull a01 = 0, a23 = 0, a45 = 0, a67 = 0;
            float nq = -3.0e38f;                 // invalid rows -> ex2 underflows to 0
            if (gi < P) {
                const ulonglong2* r = (const ulonglong2*)&g_cp_emb[b][gi][0];
                ulonglong2 u = r[0], v = r[1];
                a01 = u.x; a23 = u.y; a45 = v.x; a67 = v.y;
                nq = -g_cp_sq2[b][gi];
            }

            float acc = 0.f;
            if (tj > ti && jn == TILE) {
                // clean off-diagonal full tile: all j > all i
                #pragma unroll 4
                for (int jj = 0; jj < TILE; jj++) {
                    ulonglong2 p0 = *(const ulonglong2*)&sJ[jj][0];
                    ulonglong2 p1 = *(const ulonglong2*)&sJ[jj][2];
                    ull cch = ffma2(a67, p1.y, sJ[jj][4]);
                    cch = ffma2(a45, p1.x, cch);
                    cch = ffma2(a23, p0.y, cch);
                    cch = ffma2(a01, p0.x, cch);
                    acc += ex2f(fminf(f2sum(cch) + nq, 0.f));
                }
            } else {
                #pragma unroll 4
                for (int jj = 0; jj < jn; jj++) {
                    ulonglong2 p0 = *(const ulonglong2*)&sJ[jj][0];
                    ulonglong2 p1 = *(const ulonglong2*)&sJ[jj][2];
                    ull cch = ffma2(a67, p1.y, sJ[jj][4]);
                    cch = ffma2(a45, p1.x, cch);
                    cch = ffma2(a23, p0.y, cch);
                    cch = ffma2(a01, p0.x, cch);
                    float ex = ex2f(fminf(f2sum(cch) + nq, 0.f));
                    acc += ((j0 + jj) > gi) ? ex : 0.f;   // strict upper triangle
                }
            }

            sred[t] = acc;
            __syncthreads();
            #pragma unroll
            for (int off = TILE / 2; off > 0; off >>= 1) {
                if (t < off) sred[t] += sred[t + off];
                __syncthreads();
            }
            if (t == 0) atomicAdd(&g_repsum[b], sred[0]);
        }
    }

    // ---------------- global election ----------------
    __threadfence();
    __syncthreads();
    if (t == 0) {
        int old = atomicAdd(&g_done, 1);
        s_last = (old == G2 - 1);
    }
    __syncthreads();
    if (!s_last) return;
    __threadfence();

    // ======== finalize (one block; warp w handles batch w) ========
    {
        const int b = t >> 5;       // 4 warps, one per batch
        float attr = 0.f;
        #pragma unroll
        for (int qq = 0; qq < KK / 32; qq++) {
            int k = lane + qq * 32;
            int m   = g_firstmax[b][k];
            int cnt = g_cnt[b][k];
            float seg = g_seg[b][k];
            attr += (m > 0 && cnt > 0) ? seg / fmaxf((float)cnt, 1.f) : 0.f;
        }
        #pragma unroll
        for (int off = 16; off; off >>= 1)
            attr += __shfl_down_sync(0xffffffffu, attr, off);
        if (lane == 0) {
            float pos = (float)s_P[b];
            float neg = (float)NN - pos;
            int   valid = (pos >= 1.f) && (neg >= 1.f);
            float pw  = neg / (pos + 1e-6f);
            float bce = (pw * g_bce1[b] + g_bce0[b]) / (float)NN;
            float S   = g_repsum[b];
            float rep_sum = pos + 2.f * S;                 // diagonal = pos exactly
            float rep = (pos > 1.f) ? rep_sum / fmaxf(pos * pos, 1.f) : 0.f;
            sred[b]     = valid ? (bce + attr + rep) : 0.f;
            sred[4 + b] = valid ? 1.f : 0.f;
        }
    }
    __syncthreads();
    if (t == 0) {
        float ts = 0.f, cnt = 0.f;
        #pragma unroll
        for (int bb = 0; bb < BB; bb++) { ts += sred[bb]; cnt += sred[4 + bb]; }
        out[0] = (cnt > 0.f) ? ts / fmaxf(cnt, 1.f) : 0.f;
    }
    __syncthreads();
    // reset all accumulators for the next graph replay
    for (int idx = t; idx < BB * KK; idx += TILE) {
        int bb = idx >> 6, k = idx & 63;
        g_cnt[bb][k]      = 0;
        g_firstmax[bb][k] = 0;
        g_seg[bb][k]      = 0.f;
    }
    if (t < BB) {
        g_pos[t]    = 0;
        g_repsum[t] = 0.f;
        g_bce1[t]   = 0.f;
        g_bce0[t]   = 0.f;
    }
    if (t == 0) g_done = 0;
}

// ================= launch =================
extern "C" void kernel_launch(void* const* d_in, const int* in_sizes, int n_in,
                              void* d_out, int out_size)
{
    const float* beta  = (const float*)d_in[0];
    const float* embed = (const float*)d_in[1];
    const int*   sid   = (const int*)  d_in[2];
    const int*   iscp  = (const int*)  d_in[3];
    float* out = (float*)d_out;

    dim3 g1(CC1, BB);
    k_pass1<<<g1, CH1>>>(beta, embed, sid, iscp);
    k_main<<<G2, TILE>>>(embed, sid, out);
}